// round 13
// baseline (speedup 1.0000x reference)
#include <cuda_runtime.h>
#include <math.h>

#define NN    96
#define INDIM 64
#define HID   256
#define ZDIM  64
#define TRIN  4656
#define GRIDN 96
#define NT    192
#define NROUND 25
#define MAXR  32                   // max rows handled (degree+1 <= 32)
#define FSTR  32                   // flag stride in ints -> 128B per flag line

// ------------- persistent device scratch (no allocations allowed) -------------
__device__ int   g_flag[GRIDN * FSTR];     // padded per-block monotonic counters
__device__ float g_dis[NN];
__device__ float g_degA[NN];
__device__ float g_tmp1[NN * HID];
__device__ float g_tmp2[NN * HID];
__device__ __align__(16) float g_vecb[TRIN];
__device__ __align__(16) float g_B[NN * NN];
__device__ float g_Bd[NN];
__device__ float g_degB[NN];
__device__ float g_rec[NN];
__device__ float g_part[NROUND * NN];
__device__ __align__(16) float g_M[2 * NN * NN];   // ping-pong published max-rows
__device__ __align__(16) float g_X[2 * NN * NN];   // ping-pong published state rows

// ---- release/acquire primitives (NO single-address atomics anywhere) ----
__device__ __forceinline__ int ld_acq(const int* p) {
    int v; asm volatile("ld.acquire.gpu.global.s32 %0, [%1];" : "=r"(v) : "l"(p)); return v;
}
__device__ __forceinline__ void st_rel(int* p, int v) {
    asm volatile("st.release.gpu.global.s32 [%0], %1;" :: "l"(p), "r"(v) : "memory");
}

__device__ __forceinline__ void wait_all(int tgt) {
    if (threadIdx.x < 32) {
        for (;;) {
            int ok = 1;
            #pragma unroll
            for (int i = 0; i < 3; i++)
                ok &= (ld_acq(&g_flag[(threadIdx.x + 32 * i) * FSTR]) >= tgt);
            if (__all_sync(0xFFFFFFFFu, ok)) break;
        }
    }
    __syncthreads();
}

__device__ __forceinline__ void gbar(int base, int& ph) {
    int tgt = base + (++ph);
    __syncthreads();
    if (threadIdx.x == 0) st_rel(&g_flag[blockIdx.x * FSTR], tgt);
    wait_all(tgt);
}

__device__ __forceinline__ float blk_sum(float v, volatile float* s_w) {
    __syncthreads();
    #pragma unroll
    for (int o = 16; o; o >>= 1) v += __shfl_down_sync(0xFFFFFFFFu, v, o);
    if ((threadIdx.x & 31) == 0) s_w[threadIdx.x >> 5] = v;
    __syncthreads();
    return ((s_w[0] + s_w[1]) + (s_w[2] + s_w[3])) + (s_w[4] + s_w[5]);
}

extern "C" __global__ void __launch_bounds__(NT, 1)
gvae_kernel(const float* __restrict__ X, const int* __restrict__ EI, int E,
            const float* __restrict__ A,
            const float* __restrict__ W1, const float* __restrict__ B1,
            const float* __restrict__ G1, const float* __restrict__ BB1,
            const float* __restrict__ W2, const float* __restrict__ B2,
            const float* __restrict__ G2, const float* __restrict__ BB2,
            const float* __restrict__ MUW, const float* __restrict__ MUB,
            const float* __restrict__ LVW, const float* __restrict__ LVB,
            const float* __restrict__ D1W, const float* __restrict__ D1B,
            const float* __restrict__ D2W, const float* __restrict__ D2B,
            const float* __restrict__ EPS, float* __restrict__ OUT, int osz)
{
    const int bid = blockIdx.x, tid = threadIdx.x;
    const int wrp = tid >> 5, lane = tid & 31;
    __shared__ int   s_cnt[NN];
    __shared__ float s_An[NN];
    __shared__ float s_row[HID];
    __shared__ float s_g[HID];
    __shared__ float s_mu[NT], s_lv[NT];
    __shared__ float s_z[ZDIM];
    __shared__ float s_d1[HID];
    __shared__ __align__(16) float4 s_dec[104];
    __shared__ __align__(16) float s_x[NN];
    __shared__ __align__(16) float s_Bd[NN];
    __shared__ float s_dgB[NN];
    __shared__ int   s_nbr[NN];
    __shared__ int   s_wcnt[6];
    __shared__ int   s_nnb;
    __shared__ int   s_rows[MAXR];
    __shared__ int   s_cnt2r[MAXR];
    __shared__ float s_adg[MAXR];
    __shared__ float s_dga[MAXR];
    __shared__ int   s_nbr2[MAXR * 32];
    __shared__ __align__(16) float s_xn[MAXR * NN];
    __shared__ __align__(16) float s_Mn[MAXR * NN];
    __shared__ volatile float s_w[6];
    __shared__ float s_degA;

    int base = ld_acq(&g_flag[bid * FSTR]);
    int ph = 0;

    // ==== S1: own-row edge count, deg->dis, degA, rowmm1 ====
    if (tid < NN) s_cnt[tid] = 0;
    if (tid < INDIM) s_row[tid] = X[bid * INDIM + tid];
    __syncthreads();
    for (int e = tid; e < E; e += NT)
        if (EI[E + e] == bid) atomicAdd(&s_cnt[EI[e]], 1);
    __syncthreads();
    if (tid == 0) s_cnt[bid] += 1;                     // self loop
    __syncthreads();
    {
        float dg = blk_sum((tid < NN) ? (float)s_cnt[tid] : 0.f, s_w);
        float dA = blk_sum((tid < NN) ? A[bid * NN + tid] : 0.f, s_w);
        if (tid == 0) { g_dis[bid] = rsqrtf(dg); s_degA = dA; g_degA[bid] = dA; }
    }
    for (int f = tid; f < HID; f += NT) {
        float a0 = 0.f;
        #pragma unroll 8
        for (int k = 0; k < INDIM; k++) a0 += s_row[k] * W1[k * HID + f];
        g_tmp1[bid * HID + f] = a0;
    }
    gbar(base, ph);                                    // 1

    // ==== S2: An row + agg1 (+B1) ====
    {
        float db = __ldcg(&g_dis[bid]);
        if (tid < NN) s_An[tid] = db * __ldcg(&g_dis[tid]) * (float)s_cnt[tid];
    }
    __syncthreads();
    for (int f = tid; f < HID; f += NT) {
        float a0 = 0.f;
        #pragma unroll 8
        for (int s = 0; s < NN; s++) a0 += s_An[s] * __ldcg(&g_tmp1[s * HID + f]);
        g_tmp2[bid * HID + f] = B1[f] + a0;
    }
    gbar(base, ph);                                    // 2

    // ==== S3: redundant BN1 stats + BN+relu own row -> rowmm2 ====
    for (int f = tid; f < HID; f += NT) {
        float s0 = 0.f, q0 = 0.f;
        #pragma unroll 4
        for (int n = 0; n < NN; n++) {
            float a = __ldcg(&g_tmp2[n * HID + f]);
            s0 += a; q0 += a * a;
        }
        float m0 = s0 * (1.0f / NN);
        float va = q0 * (1.0f / NN) - m0 * m0;
        float v  = __ldcg(&g_tmp2[bid * HID + f]);
        float sc = G1[f] * rsqrtf(va + 1e-5f);
        s_row[f] = fmaxf((v - m0) * sc + BB1[f], 0.f);
    }
    __syncthreads();
    for (int f = tid; f < HID; f += NT) {
        float a0 = 0.f;
        #pragma unroll 8
        for (int k = 0; k < HID; k++) a0 += s_row[k] * W2[k * HID + f];
        g_tmp1[bid * HID + f] = a0;
    }
    gbar(base, ph);                                    // 3

    // ==== S4: agg2 (+B2) ====
    for (int f = tid; f < HID; f += NT) {
        float a0 = 0.f;
        #pragma unroll 8
        for (int s = 0; s < NN; s++) a0 += s_An[s] * __ldcg(&g_tmp1[s * HID + f]);
        g_tmp2[bid * HID + f] = B2[f] + a0;
    }
    gbar(base, ph);                                    // 4

    // ==== S5: redundant BN2+pool; replicated VAE head + dec1 + dec2 chunk ====
    for (int f = tid; f < HID; f += NT) {
        float s0 = 0.f, q0 = 0.f;
        #pragma unroll 4
        for (int n = 0; n < NN; n++) {
            float a = __ldcg(&g_tmp2[n * HID + f]);
            s0 += a; q0 += a * a;
        }
        float m0 = s0 * (1.0f / NN);
        float va = q0 * (1.0f / NN) - m0 * m0;
        float sc = G2[f] * rsqrtf(va + 1e-5f);
        float bb = BB2[f];
        float gp = 0.f;
        #pragma unroll 4
        for (int n = 0; n < NN; n++) {
            float a = __ldcg(&g_tmp2[n * HID + f]);
            gp += fmaxf((a - m0) * sc + bb, 0.f);
        }
        s_g[f] = gp;
    }
    __syncthreads();
    {
        int z = tid % 64, seg = tid / 64;              // 3-way k split
        int k0 = (seg * HID) / 3, k1 = ((seg + 1) * HID) / 3;
        float amu = 0.f, alv = 0.f;
        #pragma unroll 8
        for (int k = k0; k < k1; k++) {
            float gv = s_g[k];
            amu += gv * MUW[k * ZDIM + z];
            alv += gv * LVW[k * ZDIM + z];
        }
        s_mu[tid] = amu; s_lv[tid] = alv;
    }
    __syncthreads();
    float klv;
    {
        float klt = 0.f;
        if (tid < ZDIM) {
            float mu = s_mu[tid] + s_mu[tid + 64] + s_mu[tid + 128] + MUB[tid];
            float lv = s_lv[tid] + s_lv[tid + 64] + s_lv[tid + 128] + LVB[tid];
            s_z[tid] = mu + EPS[tid] * expf(0.5f * lv);
            klt = 1.f + lv - mu * mu - expf(lv);
        }
        klv = -0.5f * blk_sum(klt, s_w) * (1.0f / ZDIM);
    }
    for (int f = tid; f < HID; f += NT) {
        float a0 = D1B[f];
        #pragma unroll 8
        for (int k = 0; k < ZDIM; k++) a0 += s_z[k] * D1W[k * HID + f];
        s_d1[f] = fmaxf(a0, 0.f);
    }
    __syncthreads();
    {
        const int ng = (bid < 12) ? 13 : 12;
        const int g0 = bid * 12 + (bid < 12 ? bid : 12);
        if (tid < ng * 8) {
            int grp = tid >> 3, kq = tid & 7;
            int g4 = g0 + grp;
            const float4* W4 = (const float4*)D2W;
            float ax = 0.f, ay = 0.f, az = 0.f, aw = 0.f;
            #pragma unroll 8
            for (int k = kq * 32; k < kq * 32 + 32; k++) {
                float dv = s_d1[k];
                float4 w = __ldcg(&W4[k * (TRIN / 4) + g4]);
                ax += dv * w.x; ay += dv * w.y; az += dv * w.z; aw += dv * w.w;
            }
            s_dec[tid] = make_float4(ax, ay, az, aw);
        }
        __syncthreads();
        if (tid < ng) {
            float4 a = s_dec[tid * 8];
            #pragma unroll
            for (int j = 1; j < 8; j++) {
                float4 b = s_dec[tid * 8 + j];
                a.x += b.x; a.y += b.y; a.z += b.z; a.w += b.w;
            }
            float4 bb = __ldcg(&((const float4*)D2B)[g0 + tid]);
            a.x += bb.x; a.y += bb.y; a.z += bb.z; a.w += bb.w;
            ((float4*)g_vecb)[g0 + tid] = a;
        }
    }
    gbar(base, ph);                                    // 5

    // ==== S6: build B row, Bd, degB, BCE partial ====
    {
        float Bv = 0.f, rc = 0.f;
        if (tid < NN) {
            int i_ = bid < tid ? bid : tid;
            int j_ = bid < tid ? tid : bid;
            int o  = i_ * NN - (i_ * (i_ - 1)) / 2 + (j_ - i_);
            float v = __ldcg(&g_vecb[o]);
            Bv = 1.f / (1.f + expf(-v));
            g_B[bid * NN + tid] = Bv;
            if (tid == bid) g_Bd[bid] = Bv;
            if (tid >= bid) {
                float truth = A[bid * NN + tid];
                rc = fmaxf(v, 0.f) - v * truth + log1pf(expf(-fabsf(v)));
            }
        }
        float dB = blk_sum(Bv, s_w);
        float rs = blk_sum(rc, s_w);
        if (tid == 0) { g_degB[bid] = dB; g_rec[bid] = rs; }
    }
    gbar(base, ph);                                    // 6

    // ==== MPM setup ====
    if (tid < NN) { s_Bd[tid] = __ldcg(&g_Bd[tid]); s_dgB[tid] = __ldcg(&g_degB[tid]); }
    {
        bool pred = (tid < NN) && (tid != bid) && (A[bid * NN + tid] != 0.f);
        unsigned mm = __ballot_sync(0xFFFFFFFFu, pred);
        if (lane == 0) s_wcnt[wrp] = __popc(mm);
        __syncthreads();
        int bpos = 0;
        #pragma unroll
        for (int ww = 0; ww < 6; ww++) if (ww < wrp) bpos += s_wcnt[ww];
        if (pred) s_nbr[bpos + __popc(mm & ((1u << lane) - 1u))] = tid;
        __syncthreads();
        if (tid == 0) {
            int c = 0;
            #pragma unroll
            for (int ww = 0; ww < 6; ww++) c += s_wcnt[ww];
            s_nnb = (c > MAXR - 1) ? (MAXR - 1) : c;
        }
    }
    __syncthreads();
    const int nnb = s_nnb;
    const int nr  = nnb + 1;
    if (tid < nnb) s_rows[tid] = s_nbr[tid];
    if (tid == 0)  s_rows[nnb] = bid;
    __syncthreads();
    // per-row metadata + inner neighbor lists (6 warps stride rows)
    for (int r = wrp; r < nr; r += 6) {
        int j = s_rows[r];
        int cnt = 0;
        #pragma unroll
        for (int seg = 0; seg < 3; seg++) {
            int m = seg * 32 + lane;
            bool pr = (m != j) && (A[j * NN + m] != 0.f);
            unsigned bal = __ballot_sync(0xFFFFFFFFu, pr);
            int idx = cnt + __popc(bal & ((1u << lane) - 1u));
            if (pr && idx < 32) s_nbr2[r * 32 + idx] = m;
            cnt += __popc(bal);
        }
        if (lane == 0) {
            s_cnt2r[r] = (cnt > 32) ? 32 : cnt;
            s_adg[r]   = A[j * NN + j];
            s_dga[r]   = __ldcg(&g_degA[j]);
        }
    }
    __syncthreads();

    // Q full row in registers: aq = tid % 96 (two copies, g = tid/96)
    const int aq = tid % NN, gq = tid / NN;
    float4 q4[24];
    {
        float Bda = s_Bd[aq];
        const float4* br  = (const float4*)(g_B + aq * NN);
        const float4* sd4 = (const float4*)s_Bd;
        #pragma unroll
        for (int b4 = 0; b4 < 24; b4++) {
            float4 bv = __ldcg(&br[b4]);
            float4 sd = sd4[b4];
            int b = 4 * b4;
            float4 qv;
            qv.x = (b + 0 == aq) ? 0.f : bv.x * Bda * sd.x;
            qv.y = (b + 1 == aq) ? 0.f : bv.y * Bda * sd.y;
            qv.z = (b + 2 == aq) ? 0.f : bv.z * Bda * sd.z;
            qv.w = (b + 3 == aq) ? 0.f : bv.w * Bda * sd.w;
            q4[b4] = qv;
        }
    }
    float Da = 0.f;
    if (tid < NN) {
        Da = A[bid * NN + bid] * s_Bd[tid] /
             (fabsf(s_degA - s_dgB[tid]) + 1.f);
        s_x[tid] = 1.0f / (float)NN;
    }
    __syncthreads();

    // ==== MPM: 25 rounds of 2 iterations, ONE global handoff per round ====
    for (int t = 0; t < NROUND; t++) {
        float* Mp = g_M + (t & 1) * (NN * NN);
        float* Xp = g_X + (t & 1) * (NN * NN);
        // publish own M row (phase A of current x) and x row
        if (tid < NN) {
            const float4* sx4 = (const float4*)s_x;
            float m0 = 0.f, m1 = 0.f, m2 = 0.f, m3 = 0.f;
            #pragma unroll
            for (int b4 = 0; b4 < 24; b4++) {
                float4 xv = sx4[b4];
                float4 qv = q4[b4];
                m0 = fmaxf(m0, qv.x * xv.x);
                m1 = fmaxf(m1, qv.y * xv.y);
                m2 = fmaxf(m2, qv.z * xv.z);
                m3 = fmaxf(m3, qv.w * xv.w);
            }
            Mp[bid * NN + tid] = fmaxf(fmaxf(m0, m1), fmaxf(m2, m3));
            Xp[bid * NN + tid] = s_x[tid];
        }
        __syncthreads();
        int tgt = base + (++ph);
        if (tid == 0) st_rel(&g_flag[bid * FSTR], tgt);
        wait_all(tgt);

        // step B: reconstruct x^{k+1} for rows N(i) U {i}
        // (bitwise identical across blocks: same published inputs, same order)
        for (int it = tid; it < nr * NN; it += NT) {
            int r = it / NN, a = it - r * NN;
            float dj = s_adg[r] * s_Bd[a] / (fabsf(s_dga[r] - s_dgB[a]) + 1.f);
            float acc = dj * __ldcg(&Xp[s_rows[r] * NN + a]);
            int c = s_cnt2r[r];
            const int* nl = s_nbr2 + r * 32;
            int l = 0;
            for (; l + 4 <= c; l += 4)
                acc = acc + __ldcg(&Mp[nl[l] * NN + a]) + __ldcg(&Mp[nl[l + 1] * NN + a])
                          + __ldcg(&Mp[nl[l + 2] * NN + a]) + __ldcg(&Mp[nl[l + 3] * NN + a]);
            for (; l < c; l++) acc += __ldcg(&Mp[nl[l] * NN + a]);
            s_xn[it] = acc;
        }
        __syncthreads();

        // step C: local phase A for neighbor rows
        for (int r = gq; r < nnb; r += 2) {
            const float4* xr = (const float4*)(s_xn + r * NN);
            float m0 = 0.f, m1 = 0.f, m2 = 0.f, m3 = 0.f;
            #pragma unroll
            for (int b4 = 0; b4 < 24; b4++) {
                float4 xv = xr[b4];
                float4 qv = q4[b4];
                m0 = fmaxf(m0, qv.x * xv.x);
                m1 = fmaxf(m1, qv.y * xv.y);
                m2 = fmaxf(m2, qv.z * xv.z);
                m3 = fmaxf(m3, qv.w * xv.w);
            }
            s_Mn[r * NN + aq] = fmaxf(fmaxf(m0, m1), fmaxf(m2, m3));
        }
        __syncthreads();

        // step D: combine own x^{k+2}
        float xn = 0.f;
        if (tid < NN) {
            float acc = Da * s_xn[nnb * NN + tid];
            for (int r = 0; r < nnb; r++) acc += s_Mn[r * NN + tid];
            xn = acc;
        }

        // norm partial (pre-scale) + STALE-BY-1 renorm (stable recursion
        // u_t = g + u_{t-1} - u_{t-2}: unit-circle roots, bounded oscillation;
        // exact by homogeneity + true final normalize)
        float p = blk_sum(xn * xn, s_w);
        if (tid == 0) g_part[t * NN + bid] = p;
        if (t == NROUND - 1) {
            __syncthreads();
            int ft = base + (++ph);
            if (tid == 0) st_rel(&g_flag[bid * FSTR], ft);
            wait_all(ft);
            float pv   = (tid < NN) ? __ldcg(&g_part[(NROUND - 1) * NN + tid]) : 0.f;
            float invn = rsqrtf(blk_sum(pv, s_w));
            int off = (osz > NN * NN) ? (osz - NN * NN) : 0;
            if (osz >= NN * NN && tid < NN)
                OUT[off + bid * NN + tid] = xn * invn;
            if (bid == 0) {
                float rp = (tid < NN) ? __ldcg(&g_rec[tid]) : 0.f;
                float rs = blk_sum(rp, s_w);
                if (tid == 0 && (osz < NN * NN || off > 0))
                    OUT[0] = rs * (1.0f / (float)TRIN) + klv;
            }
            return;
        }
        if (t >= 1) {
            float pv   = (tid < NN) ? __ldcg(&g_part[(t - 1) * NN + tid]) : 0.f;
            float invn = rsqrtf(blk_sum(pv, s_w));
            xn *= invn;
        }
        if (tid < NN) s_x[tid] = xn;
        __syncthreads();
    }
}

extern "C" void kernel_launch(void* const* d_in, const int* in_sizes, int n_in,
                              void* d_out, int out_size) {
    const float* X   = (const float*)d_in[0];
    const int*   EI  = (const int*)  d_in[1];
    const float* A   = (const float*)d_in[3];
    const float* W1  = (const float*)d_in[4];
    const float* B1  = (const float*)d_in[5];
    const float* G1  = (const float*)d_in[6];
    const float* BB1 = (const float*)d_in[7];
    const float* W2  = (const float*)d_in[8];
    const float* B2  = (const float*)d_in[9];
    const float* G2  = (const float*)d_in[10];
    const float* BB2 = (const float*)d_in[11];
    const float* MUW = (const float*)d_in[12];
    const float* MUB = (const float*)d_in[13];
    const float* LVW = (const float*)d_in[14];
    const float* LVB = (const float*)d_in[15];
    const float* D1W = (const float*)d_in[16];
    const float* D1B = (const float*)d_in[17];
    const float* D2W = (const float*)d_in[18];
    const float* D2B = (const float*)d_in[19];
    const float* EPS = (const float*)d_in[20];
    int E = in_sizes[1] / 2;

    gvae_kernel<<<GRIDN, NT>>>(X, EI, E, A, W1, B1, G1, BB1, W2, B2, G2, BB2,
                               MUW, MUB, LVW, LVB, D1W, D1B, D2W, D2B, EPS,
                               (float*)d_out, out_size);
}

// round 14
// speedup vs baseline: 2.8092x; 2.8092x over previous
#include <cuda_runtime.h>
#include <math.h>

#define NN    96
#define INDIM 64
#define HID   256
#define ZDIM  64
#define TRIN  4656
#define GRIDN 96
#define NT    192
#define ITERS 50
#define MSLOT ((NN + 1) * NN)      // row 96 = permanent zero pad
#define FSTR  32                   // flag stride in ints -> 128B per flag line

// ------------- persistent device scratch (no allocations allowed) -------------
__device__ int   g_flag[GRIDN * FSTR];     // padded per-block monotonic counters
__device__ float g_dis[NN];
__device__ float g_tmp1[NN * HID];
__device__ float g_tmp2[NN * HID];
__device__ __align__(16) float g_vecb[TRIN];
__device__ __align__(16) float g_B[NN * NN];
__device__ float g_Bd[NN];
__device__ float g_degB[NN];
__device__ float g_rec[NN];
__device__ float g_part[10 * NN];          // one slot per 5-iter checkpoint
__device__ float g_M[2 * MSLOT];           // ping-pong; pad row 96 stays zero

// ---- release/acquire primitives (NO single-address atomics anywhere) ----
__device__ __forceinline__ int ld_acq(const int* p) {
    int v; asm volatile("ld.acquire.gpu.global.s32 %0, [%1];" : "=r"(v) : "l"(p)); return v;
}
__device__ __forceinline__ void st_rel(int* p, int v) {
    asm volatile("st.release.gpu.global.s32 [%0], %1;" :: "l"(p), "r"(v) : "memory");
}

__device__ __forceinline__ void wait_all(int tgt) {
    if (threadIdx.x < 32) {
        for (;;) {
            int ok = 1;
            #pragma unroll
            for (int i = 0; i < 3; i++)
                ok &= (ld_acq(&g_flag[(threadIdx.x + 32 * i) * FSTR]) >= tgt);
            if (__all_sync(0xFFFFFFFFu, ok)) break;
        }
    }
    __syncthreads();
}

__device__ __forceinline__ void wait_nbr(const int* s_nbr, int nnb, int tgt) {
    if (threadIdx.x < 32) {
        for (;;) {
            int ok = 1;
            for (int i = threadIdx.x; i < nnb; i += 32)
                ok &= (ld_acq(&g_flag[s_nbr[i] * FSTR]) >= tgt);
            if (__all_sync(0xFFFFFFFFu, ok)) break;
        }
    }
    __syncthreads();
}

__device__ __forceinline__ void gbar(int base, int& ph) {
    int tgt = base + (++ph);
    __syncthreads();
    if (threadIdx.x == 0) st_rel(&g_flag[blockIdx.x * FSTR], tgt);
    wait_all(tgt);
}

__device__ __forceinline__ float blk_sum(float v, volatile float* s_w) {
    __syncthreads();
    #pragma unroll
    for (int o = 16; o; o >>= 1) v += __shfl_down_sync(0xFFFFFFFFu, v, o);
    if ((threadIdx.x & 31) == 0) s_w[threadIdx.x >> 5] = v;
    __syncthreads();
    return ((s_w[0] + s_w[1]) + (s_w[2] + s_w[3])) + (s_w[4] + s_w[5]);
}

extern "C" __global__ void __launch_bounds__(NT, 1)
gvae_kernel(const float* __restrict__ X, const int* __restrict__ EI, int E,
            const float* __restrict__ A,
            const float* __restrict__ W1, const float* __restrict__ B1,
            const float* __restrict__ G1, const float* __restrict__ BB1,
            const float* __restrict__ W2, const float* __restrict__ B2,
            const float* __restrict__ G2, const float* __restrict__ BB2,
            const float* __restrict__ MUW, const float* __restrict__ MUB,
            const float* __restrict__ LVW, const float* __restrict__ LVB,
            const float* __restrict__ D1W, const float* __restrict__ D1B,
            const float* __restrict__ D2W, const float* __restrict__ D2B,
            const float* __restrict__ EPS, float* __restrict__ OUT, int osz)
{
    const int bid = blockIdx.x, tid = threadIdx.x;
    __shared__ int   s_cnt[NN];
    __shared__ float s_An[NN];
    __shared__ float s_row[HID];
    __shared__ float s_g[HID];
    __shared__ float s_mu[NT], s_lv[NT];
    __shared__ float s_z[ZDIM];
    __shared__ float s_d1[HID];
    __shared__ __align__(16) float4 s_dec[104];
    __shared__ __align__(16) float s_x[NN];
    __shared__ __align__(16) float s_Bd[NN];
    __shared__ int   s_nbr[NN + 16];
    __shared__ int   s_wcnt[6];
    __shared__ int   s_cnt2[2];
    __shared__ volatile float s_w[6];
    __shared__ float s_degA;

    int base = ld_acq(&g_flag[bid * FSTR]);
    int ph = 0;

    // ==== S1: own-row edge count, deg->dis, degA, rowmm1; init MPM pads ====
    if (tid < NN) s_cnt[tid] = 0;
    if (tid < INDIM) s_row[tid] = X[bid * INDIM + tid];
    if (bid == 0 && tid < NN) g_M[NN * NN + tid] = 0.f;
    if (bid == 1 && tid < NN) g_M[MSLOT + NN * NN + tid] = 0.f;
    __syncthreads();
    for (int e = tid; e < E; e += NT)
        if (EI[E + e] == bid) atomicAdd(&s_cnt[EI[e]], 1);
    __syncthreads();
    if (tid == 0) s_cnt[bid] += 1;                     // self loop
    __syncthreads();
    {
        float dg = blk_sum((tid < NN) ? (float)s_cnt[tid] : 0.f, s_w);
        float dA = blk_sum((tid < NN) ? A[bid * NN + tid] : 0.f, s_w);
        if (tid == 0) { g_dis[bid] = rsqrtf(dg); s_degA = dA; }
    }
    for (int f = tid; f < HID; f += NT) {
        float a0 = 0.f;
        #pragma unroll 8
        for (int k = 0; k < INDIM; k++) a0 += s_row[k] * W1[k * HID + f];
        g_tmp1[bid * HID + f] = a0;
    }
    gbar(base, ph);                                    // 1

    // ==== S2: An row + agg1 (+B1) ====
    {
        float db = __ldcg(&g_dis[bid]);
        if (tid < NN) s_An[tid] = db * __ldcg(&g_dis[tid]) * (float)s_cnt[tid];
    }
    __syncthreads();
    for (int f = tid; f < HID; f += NT) {
        float a0 = 0.f;
        #pragma unroll 8
        for (int s = 0; s < NN; s++) a0 += s_An[s] * __ldcg(&g_tmp1[s * HID + f]);
        g_tmp2[bid * HID + f] = B1[f] + a0;
    }
    gbar(base, ph);                                    // 2

    // ==== S3: redundant BN1 stats + BN+relu own row -> rowmm2 ====
    for (int f = tid; f < HID; f += NT) {
        float s0 = 0.f, q0 = 0.f;
        #pragma unroll 4
        for (int n = 0; n < NN; n++) {
            float a = __ldcg(&g_tmp2[n * HID + f]);
            s0 += a; q0 += a * a;
        }
        float m0 = s0 * (1.0f / NN);
        float va = q0 * (1.0f / NN) - m0 * m0;
        float v  = __ldcg(&g_tmp2[bid * HID + f]);
        float sc = G1[f] * rsqrtf(va + 1e-5f);
        s_row[f] = fmaxf((v - m0) * sc + BB1[f], 0.f);
    }
    __syncthreads();
    for (int f = tid; f < HID; f += NT) {
        float a0 = 0.f;
        #pragma unroll 8
        for (int k = 0; k < HID; k++) a0 += s_row[k] * W2[k * HID + f];
        g_tmp1[bid * HID + f] = a0;
    }
    gbar(base, ph);                                    // 3

    // ==== S4: agg2 (+B2) ====
    for (int f = tid; f < HID; f += NT) {
        float a0 = 0.f;
        #pragma unroll 8
        for (int s = 0; s < NN; s++) a0 += s_An[s] * __ldcg(&g_tmp1[s * HID + f]);
        g_tmp2[bid * HID + f] = B2[f] + a0;
    }
    gbar(base, ph);                                    // 4

    // ==== S5: redundant BN2+pool; replicated VAE head + dec1 + dec2 chunk ====
    for (int f = tid; f < HID; f += NT) {
        float s0 = 0.f, q0 = 0.f;
        #pragma unroll 4
        for (int n = 0; n < NN; n++) {
            float a = __ldcg(&g_tmp2[n * HID + f]);
            s0 += a; q0 += a * a;
        }
        float m0 = s0 * (1.0f / NN);
        float va = q0 * (1.0f / NN) - m0 * m0;
        float sc = G2[f] * rsqrtf(va + 1e-5f);
        float bb = BB2[f];
        float gp = 0.f;
        #pragma unroll 4
        for (int n = 0; n < NN; n++) {
            float a = __ldcg(&g_tmp2[n * HID + f]);
            gp += fmaxf((a - m0) * sc + bb, 0.f);
        }
        s_g[f] = gp;
    }
    __syncthreads();
    {
        int z = tid % 64, seg = tid / 64;              // 3-way k split
        int k0 = (seg * HID) / 3, k1 = ((seg + 1) * HID) / 3;
        float amu = 0.f, alv = 0.f;
        #pragma unroll 8
        for (int k = k0; k < k1; k++) {
            float gv = s_g[k];
            amu += gv * MUW[k * ZDIM + z];
            alv += gv * LVW[k * ZDIM + z];
        }
        s_mu[tid] = amu; s_lv[tid] = alv;
    }
    __syncthreads();
    float klv;
    {
        float klt = 0.f;
        if (tid < ZDIM) {
            float mu = s_mu[tid] + s_mu[tid + 64] + s_mu[tid + 128] + MUB[tid];
            float lv = s_lv[tid] + s_lv[tid + 64] + s_lv[tid + 128] + LVB[tid];
            s_z[tid] = mu + EPS[tid] * expf(0.5f * lv);
            klt = 1.f + lv - mu * mu - expf(lv);
        }
        klv = -0.5f * blk_sum(klt, s_w) * (1.0f / ZDIM);
    }
    for (int f = tid; f < HID; f += NT) {
        float a0 = D1B[f];
        #pragma unroll 8
        for (int k = 0; k < ZDIM; k++) a0 += s_z[k] * D1W[k * HID + f];
        s_d1[f] = fmaxf(a0, 0.f);
    }
    __syncthreads();
    {
        const int ng = (bid < 12) ? 13 : 12;
        const int g0 = bid * 12 + (bid < 12 ? bid : 12);
        if (tid < ng * 8) {
            int grp = tid >> 3, kq = tid & 7;
            int g4 = g0 + grp;
            const float4* W4 = (const float4*)D2W;
            float ax = 0.f, ay = 0.f, az = 0.f, aw = 0.f;
            #pragma unroll 8
            for (int k = kq * 32; k < kq * 32 + 32; k++) {
                float dv = s_d1[k];
                float4 w = __ldcg(&W4[k * (TRIN / 4) + g4]);
                ax += dv * w.x; ay += dv * w.y; az += dv * w.z; aw += dv * w.w;
            }
            s_dec[tid] = make_float4(ax, ay, az, aw);
        }
        __syncthreads();
        if (tid < ng) {
            float4 a = s_dec[tid * 8];
            #pragma unroll
            for (int j = 1; j < 8; j++) {
                float4 b = s_dec[tid * 8 + j];
                a.x += b.x; a.y += b.y; a.z += b.z; a.w += b.w;
            }
            float4 bb = __ldcg(&((const float4*)D2B)[g0 + tid]);
            a.x += bb.x; a.y += bb.y; a.z += bb.z; a.w += bb.w;
            ((float4*)g_vecb)[g0 + tid] = a;
        }
    }
    gbar(base, ph);                                    // 5

    // ==== S6: build B row, Bd, degB, BCE partial ====
    {
        float Bv = 0.f, rc = 0.f;
        if (tid < NN) {
            int i_ = bid < tid ? bid : tid;
            int j_ = bid < tid ? tid : bid;
            int o  = i_ * NN - (i_ * (i_ - 1)) / 2 + (j_ - i_);
            float v = __ldcg(&g_vecb[o]);
            Bv = 1.f / (1.f + expf(-v));
            g_B[bid * NN + tid] = Bv;
            if (tid == bid) g_Bd[bid] = Bv;
            if (tid >= bid) {
                float truth = A[bid * NN + tid];
                rc = fmaxf(v, 0.f) - v * truth + log1pf(expf(-fabsf(v)));
            }
        }
        float dB = blk_sum(Bv, s_w);
        float rs = blk_sum(rc, s_w);
        if (tid == 0) { g_degB[bid] = dB; g_rec[bid] = rs; }
    }
    gbar(base, ph);                                    // 6

    // ==== MPM setup: Q half-rows -> float4 regs, D, neighbor list (pad 16) ====
    if (tid < NN) s_Bd[tid] = __ldcg(&g_Bd[tid]);
    {
        bool pred = (tid < NN) && (tid != bid) && (A[bid * NN + tid] != 0.f);
        unsigned mm = __ballot_sync(0xFFFFFFFFu, pred);
        int w = tid >> 5, lane = tid & 31;
        if (lane == 0) s_wcnt[w] = __popc(mm);
        __syncthreads();
        int bpos = 0;
        #pragma unroll
        for (int ww = 0; ww < 6; ww++) if (ww < w) bpos += s_wcnt[ww];
        if (pred) s_nbr[bpos + __popc(mm & ((1u << lane) - 1u))] = tid;
        __syncthreads();
        if (tid == 0) {
            int c = 0;
            #pragma unroll
            for (int ww = 0; ww < 6; ww++) c += s_wcnt[ww];
            s_cnt2[0] = c;
            while (c & 15) s_nbr[c++] = NN;            // pad -> zero row of M
            s_cnt2[1] = c;
        }
    }
    __syncthreads();
    const int nnb  = s_cnt2[0];
    const int half = s_cnt2[1] >> 1;                   // multiple of 8

    // pair layout: a2 = column a, hh = which half (of b for phase A, of nbrs for B)
    const int a2 = tid >> 1, hh = tid & 1;
    float4 q4[12];
    {
        float Bda = s_Bd[a2];
        const float4* br  = (const float4*)(g_B + a2 * NN);
        const float4* sd4 = (const float4*)s_Bd;
        #pragma unroll
        for (int i = 0; i < 12; i++) {
            int g = hh * 12 + i, b = 4 * g;
            float4 bv = __ldcg(&br[g]);
            float4 sd = sd4[g];
            float4 qv;
            qv.x = (b + 0 == a2) ? 0.f : bv.x * Bda * sd.x;
            qv.y = (b + 1 == a2) ? 0.f : bv.y * Bda * sd.y;
            qv.z = (b + 2 == a2) ? 0.f : bv.z * Bda * sd.z;
            qv.w = (b + 3 == a2) ? 0.f : bv.w * Bda * sd.w;
            q4[i] = qv;
        }
    }
    const float Da = A[bid * NN + bid] * s_Bd[a2] /
                     (fabsf(s_degA - __ldcg(&g_degB[a2])) + 1.f);
    if (tid < NN) s_x[tid] = 1.0f / (float)NN;
    __syncthreads();

    // ==== MPM: 1 bump + light neighbor-wait per iter; ONE-wave pair gather ====
    for (int k = 0; k < ITERS; k++) {
        float* Mb = g_M + (k & 1) * MSLOT;
        // phase A (all 192 threads): pair-split max over b, combine via shfl
        {
            const float4* sx4 = (const float4*)s_x + hh * 12;
            float m0 = 0.f, m1 = 0.f, m2 = 0.f, m3 = 0.f;
            #pragma unroll
            for (int i = 0; i < 12; i++) {
                float4 xv = sx4[i];
                float4 qv = q4[i];
                m0 = fmaxf(m0, qv.x * xv.x);
                m1 = fmaxf(m1, qv.y * xv.y);
                m2 = fmaxf(m2, qv.z * xv.z);
                m3 = fmaxf(m3, qv.w * xv.w);
            }
            float m = fmaxf(fmaxf(m0, m1), fmaxf(m2, m3));
            m = fmaxf(m, __shfl_xor_sync(0xFFFFFFFFu, m, 1));
            if (hh == 0) Mb[bid * NN + a2] = m;
        }
        __syncthreads();
        int tgt = base + (++ph);
        if (tid == 0) st_rel(&g_flag[bid * FSTR], tgt);
        wait_nbr(s_nbr, nnb, tgt);

        // phase B (all 192): pair-split neighbor gather, 8 loads/thread, 1 L2 wave
        float msg = 0.f;
        {
            const int j0 = hh * half, j1 = j0 + half;
            for (int j = j0; j < j1; j += 8) {
                float t0 = __ldcg(&Mb[s_nbr[j + 0] * NN + a2]);
                float t1 = __ldcg(&Mb[s_nbr[j + 1] * NN + a2]);
                float t2 = __ldcg(&Mb[s_nbr[j + 2] * NN + a2]);
                float t3 = __ldcg(&Mb[s_nbr[j + 3] * NN + a2]);
                float t4 = __ldcg(&Mb[s_nbr[j + 4] * NN + a2]);
                float t5 = __ldcg(&Mb[s_nbr[j + 5] * NN + a2]);
                float t6 = __ldcg(&Mb[s_nbr[j + 6] * NN + a2]);
                float t7 = __ldcg(&Mb[s_nbr[j + 7] * NN + a2]);
                msg += ((t0 + t1) + (t2 + t3)) + ((t4 + t5) + (t6 + t7));
            }
        }
        msg += __shfl_xor_sync(0xFFFFFFFFu, msg, 1);
        float xn = (hh == 0) ? s_x[a2] * Da + msg : 0.f;

        if ((k % 5) == 4) {
            int r = k / 5;
            float p = blk_sum(xn * xn, s_w);           // hh==1 contributes 0
            if (tid == 0) g_part[r * NN + bid] = p;
            if (k == ITERS - 1) {
                __syncthreads();
                int ft = base + (++ph);
                if (tid == 0) st_rel(&g_flag[bid * FSTR], ft);
                wait_all(ft);
                float pv   = (tid < NN) ? __ldcg(&g_part[9 * NN + tid]) : 0.f;
                float invn = rsqrtf(blk_sum(pv, s_w));
                int off = (osz > NN * NN) ? (osz - NN * NN) : 0;
                if (osz >= NN * NN && hh == 0)
                    OUT[off + bid * NN + a2] = xn * invn;
                if (bid == 0) {
                    float rp = (tid < NN) ? __ldcg(&g_rec[tid]) : 0.f;
                    float rs = blk_sum(rp, s_w);
                    if (tid == 0 && (osz < NN * NN || off > 0))
                        OUT[0] = rs * (1.0f / (float)TRIN) + klv;
                }
                return;
            }
            if (r >= 2) {
                // stale-by-2 renorm: exact via homogeneity; visible via flag chains
                float pv   = (tid < NN) ? __ldcg(&g_part[(r - 2) * NN + tid]) : 0.f;
                float invn = rsqrtf(blk_sum(pv, s_w));
                xn *= invn;
            }
        }
        if (hh == 0) s_x[a2] = xn;
        __syncthreads();
    }
}

extern "C" void kernel_launch(void* const* d_in, const int* in_sizes, int n_in,
                              void* d_out, int out_size) {
    const float* X   = (const float*)d_in[0];
    const int*   EI  = (const int*)  d_in[1];
    const float* A   = (const float*)d_in[3];
    const float* W1  = (const float*)d_in[4];
    const float* B1  = (const float*)d_in[5];
    const float* G1  = (const float*)d_in[6];
    const float* BB1 = (const float*)d_in[7];
    const float* W2  = (const float*)d_in[8];
    const float* B2  = (const float*)d_in[9];
    const float* G2  = (const float*)d_in[10];
    const float* BB2 = (const float*)d_in[11];
    const float* MUW = (const float*)d_in[12];
    const float* MUB = (const float*)d_in[13];
    const float* LVW = (const float*)d_in[14];
    const float* LVB = (const float*)d_in[15];
    const float* D1W = (const float*)d_in[16];
    const float* D1B = (const float*)d_in[17];
    const float* D2W = (const float*)d_in[18];
    const float* D2B = (const float*)d_in[19];
    const float* EPS = (const float*)d_in[20];
    int E = in_sizes[1] / 2;

    gvae_kernel<<<GRIDN, NT>>>(X, EI, E, A, W1, B1, G1, BB1, W2, B2, G2, BB2,
                               MUW, MUB, LVW, LVB, D1W, D1B, D2W, D2B, EPS,
                               (float*)d_out, out_size);
}